// round 5
// baseline (speedup 1.0000x reference)
#include <cuda_runtime.h>
#include <math.h>

#define T_DIM 4096
#define C_DIM 1024
#define N3C   (3 * C_DIM)
#define NEG_INF_F (-1e30f)

// Scratch (device globals — no allocation in kernel_launch).
__device__ float g_q[T_DIM * C_DIM];          // 16 MB
__device__ float g_k[T_DIM * C_DIM];          // 16 MB
__device__ float g_v[T_DIM * C_DIM];          // 16 MB
__device__ float g_att[T_DIM * T_DIM];        // 64 MB

// ---------------------------------------------------------------------------
// Generic 128x128 fp32 GEMM tile: C[128,128] += A[128,kmax] * B
//   A is K-major (row-major [M,K], lda = row stride).
//   B_KMAJOR = true : B stored row-major [N,K] (ldb = K-stride)  -> computes A*B^T
//   B_KMAJOR = false: B stored row-major [K,N] (ldb = N-stride)  -> computes A*B
// 256 threads, 8x8 accumulators per thread, BK=8, single-stage prefetch.
// kmax must be a multiple of 8; all dims here are multiples of 128.
// ---------------------------------------------------------------------------
template<bool B_KMAJOR>
__device__ __forceinline__ void gemm128_tile(
    const float* __restrict__ Ablk,
    const float* __restrict__ Bblk,
    int lda, int ldb, int kmax,
    float (&acc)[8][8])
{
    __shared__ float As[8][128];
    __shared__ float Bs[8][128];

    const int tid = threadIdx.x;

    // A load: 128 rows x 8 k-cols, one float4 per thread (2 threads / row)
    const int a_row = tid >> 1;
    const int a_col = (tid & 1) << 2;
    const float* Aptr = Ablk + a_row * lda + a_col;

    // B load
    int b_r, b_c;
    const float* Bptr;
    if (B_KMAJOR) {
        b_r = tid >> 1;          // n-row 0..127
        b_c = (tid & 1) << 2;    // k-col 0 or 4
        Bptr = Bblk + b_r * ldb + b_c;
    } else {
        b_r = tid >> 5;          // k-row 0..7
        b_c = (tid & 31) << 2;   // n-col 0..124
        Bptr = Bblk + b_r * ldb + b_c;
    }

    const int tx = tid & 15;
    const int ty = tid >> 4;

    float4 areg = *(const float4*)(Aptr);
    float4 breg = *(const float4*)(Bptr);

    for (int k0 = 0; k0 < kmax; k0 += 8) {
        // regs -> smem (A transposed to [k][m])
        As[a_col + 0][a_row] = areg.x;
        As[a_col + 1][a_row] = areg.y;
        As[a_col + 2][a_row] = areg.z;
        As[a_col + 3][a_row] = areg.w;
        if (B_KMAJOR) {
            Bs[b_c + 0][b_r] = breg.x;
            Bs[b_c + 1][b_r] = breg.y;
            Bs[b_c + 2][b_r] = breg.z;
            Bs[b_c + 3][b_r] = breg.w;
        } else {
            *(float4*)&Bs[b_r][b_c] = breg;
        }
        __syncthreads();

        // prefetch next tile while computing this one
        if (k0 + 8 < kmax) {
            areg = *(const float4*)(Aptr + k0 + 8);
            if (B_KMAJOR) breg = *(const float4*)(Bptr + k0 + 8);
            else          breg = *(const float4*)(Bptr + (k0 + 8) * ldb);
        }

        #pragma unroll
        for (int kk = 0; kk < 8; kk++) {
            float a[8], b[8];
            float4 t;
            t = *(const float4*)&As[kk][ty * 4];       a[0]=t.x; a[1]=t.y; a[2]=t.z; a[3]=t.w;
            t = *(const float4*)&As[kk][64 + ty * 4];  a[4]=t.x; a[5]=t.y; a[6]=t.z; a[7]=t.w;
            t = *(const float4*)&Bs[kk][tx * 4];       b[0]=t.x; b[1]=t.y; b[2]=t.z; b[3]=t.w;
            t = *(const float4*)&Bs[kk][64 + tx * 4];  b[4]=t.x; b[5]=t.y; b[6]=t.z; b[7]=t.w;
            #pragma unroll
            for (int i = 0; i < 8; i++)
                #pragma unroll
                for (int j = 0; j < 8; j++)
                    acc[i][j] = fmaf(a[i], b[j], acc[i][j]);
        }
        __syncthreads();
    }
}

// local offset inside the 128 tile for accumulator index m (0..7)
__device__ __forceinline__ int tile_off(int m, int t4) {
    return ((m & 4) << 4) + (t4 << 2) + (m & 3);   // 0..63 or 64..127
}

// ---------------------------------------------------------------------------
// Kernel 1: qkv = x @ W + b, scattered into g_q / g_k / g_v
// grid (N3C/128, T/128)
// ---------------------------------------------------------------------------
__global__ __launch_bounds__(256) void qkv_gemm_kernel(
    const float* __restrict__ x, const float* __restrict__ W,
    const float* __restrict__ bias)
{
    const int bx = blockIdx.x, by = blockIdx.y;
    float acc[8][8] = {};
    gemm128_tile<false>(x + by * 128 * C_DIM, W + bx * 128,
                        C_DIM, N3C, C_DIM, acc);

    const int tx = threadIdx.x & 15, ty = threadIdx.x >> 4;
    const int ncol0 = bx * 128;
    const int h = ncol0 / C_DIM;                 // block fits in one of q/k/v
    float* dst = (h == 0) ? g_q : (h == 1) ? g_k : g_v;
    const int sec0 = ncol0 - h * C_DIM;

    #pragma unroll
    for (int i = 0; i < 8; i++) {
        const int r = by * 128 + tile_off(i, ty);
        #pragma unroll
        for (int j = 0; j < 8; j++) {
            const int cl = tile_off(j, tx);
            dst[r * C_DIM + sec0 + cl] = acc[i][j] + bias[ncol0 + cl];
        }
    }
}

// ---------------------------------------------------------------------------
// Kernel 2: att_raw = (q @ k^T) / sqrt(C), padding mask applied.
// Only lower-triangular tile blocks computed (bx <= by). grid (32,32).
// ---------------------------------------------------------------------------
__global__ __launch_bounds__(256) void qk_gemm_kernel(
    const int* __restrict__ n_padd_ptr)
{
    const int bx = blockIdx.x, by = blockIdx.y;
    if (bx > by) return;                          // strictly above diagonal: never read
    const int np = *n_padd_ptr;

    float acc[8][8] = {};
    gemm128_tile<true>(g_q + by * 128 * C_DIM, g_k + bx * 128 * C_DIM,
                       C_DIM, C_DIM, C_DIM, acc);

    const float scale = 0.03125f;                 // 1/sqrt(1024)
    const int tx = threadIdx.x & 15, ty = threadIdx.x >> 4;
    #pragma unroll
    for (int i = 0; i < 8; i++) {
        const int r = by * 128 + tile_off(i, ty);
        #pragma unroll
        for (int j = 0; j < 8; j++) {
            const int c = bx * 128 + tile_off(j, tx);
            float v = acc[i][j] * scale;
            if (c < np || r < np) v = NEG_INF_F;  // padding mask (causal handled in softmax)
            g_att[r * T_DIM + c] = v;
        }
    }
}

// ---------------------------------------------------------------------------
// Kernel 3: row softmax over columns [0, row]; zero-fill columns (row, T).
// One block per row.
// ---------------------------------------------------------------------------
__global__ __launch_bounds__(256) void softmax_kernel()
{
    const int r = blockIdx.x;
    float* __restrict__ row = g_att + r * T_DIM;
    const int n = r + 1;
    const int tid = threadIdx.x;
    __shared__ float red[256];

    // 1) row max
    float m = -INFINITY;
    for (int j = tid; j < n; j += 256) m = fmaxf(m, row[j]);
    red[tid] = m; __syncthreads();
    #pragma unroll
    for (int s = 128; s > 0; s >>= 1) {
        if (tid < s) red[tid] = fmaxf(red[tid], red[tid + s]);
        __syncthreads();
    }
    m = red[0];
    __syncthreads();

    // 2) exp & sum (write exp in place)
    float sum = 0.f;
    for (int j = tid; j < n; j += 256) {
        float e = expf(row[j] - m);               // -1e30 - m -> exp underflows to 0
        row[j] = e;
        sum += e;
    }
    red[tid] = sum; __syncthreads();
    #pragma unroll
    for (int s = 128; s > 0; s >>= 1) {
        if (tid < s) red[tid] += red[tid + s];
        __syncthreads();
    }
    const float inv = 1.0f / red[0];

    // 3) normalize + zero-fill the causal tail (so PV can use tile-aligned K bounds)
    for (int j = tid; j < n; j += 256) row[j] *= inv;
    for (int j = n + tid; j < T_DIM; j += 256) row[j] = 0.f;
}

// ---------------------------------------------------------------------------
// Kernel 4: y = att @ v, K bounded per query-block by causality.
// grid (C/128, T/128); row-blocks processed in reverse for wave balance.
// ---------------------------------------------------------------------------
__global__ __launch_bounds__(256) void pv_gemm_kernel(float* __restrict__ out)
{
    const int bx = blockIdx.x;
    const int by = gridDim.y - 1 - blockIdx.y;    // heavy blocks first
    const int kmax = (by + 1) * 128;              // columns > row are exactly 0

    float acc[8][8] = {};
    gemm128_tile<false>(g_att + by * 128 * T_DIM, g_v + bx * 128,
                        T_DIM, C_DIM, kmax, acc);

    const int tx = threadIdx.x & 15, ty = threadIdx.x >> 4;
    #pragma unroll
    for (int i = 0; i < 8; i++) {
        const int r = by * 128 + tile_off(i, ty);
        #pragma unroll
        for (int j = 0; j < 8; j++) {
            const int c = bx * 128 + tile_off(j, tx);
            out[r * C_DIM + c] = acc[i][j];
        }
    }
}

// ---------------------------------------------------------------------------
extern "C" void kernel_launch(void* const* d_in, const int* in_sizes, int n_in,
                              void* d_out, int out_size)
{
    const float* x    = (const float*)d_in[0];   // [T, C]
    const float* W    = (const float*)d_in[1];   // [C, 3C]
    const float* bias = (const float*)d_in[2];   // [3C]
    const int* n_padd = (const int*)d_in[3];     // scalar
    float* out = (float*)d_out;                  // [T, C]

    dim3 blk(256);
    qkv_gemm_kernel<<<dim3(N3C / 128, T_DIM / 128), blk>>>(x, W, bias);
    qk_gemm_kernel<<<dim3(T_DIM / 128, T_DIM / 128), blk>>>(n_padd);
    softmax_kernel<<<T_DIM, 256>>>();
    pv_gemm_kernel<<<dim3(C_DIM / 128, T_DIM / 128), blk>>>(out);
}

// round 8
// speedup vs baseline: 2.1781x; 2.1781x over previous
#include <cuda_runtime.h>
#include <cuda_bf16.h>
#include <cstdint>
#include <math.h>

#define T_DIM 4096
#define C_DIM 1024
#define NEG_INF_F (-1e30f)

// ============================================================================
// Scratch buffer (single device symbol). ~252 MB.
// ============================================================================
#define MB_ (1048576ull)
#define OFF_Q    (0ull)            // fp32 q        16 MB
#define OFF_K    (16*MB_)          // fp32 k        16 MB
#define OFF_V    (32*MB_)          // fp32 v        16 MB
#define OFF_ATT  (48*MB_)          // fp32 att      64 MB
#define OFF_XH   (112*MB_)
#define OFF_XL   (120*MB_)
#define OFF_WTH  (128*MB_)
#define OFF_WTL  (134*MB_)
#define OFF_QH   (140*MB_)
#define OFF_QL   (148*MB_)
#define OFF_KH   (156*MB_)
#define OFF_KL   (164*MB_)
#define OFF_VTH  (172*MB_)
#define OFF_VTL  (180*MB_)
#define OFF_ATH  (188*MB_)
#define OFF_ATL  (220*MB_)
#define BUF_TOTAL (252*MB_)

__device__ __align__(1024) char g_buf[BUF_TOTAL];

// ============================================================================
// Baseline-PTX helpers (sm_80-class: cp.async, ldmatrix, mma.sync — NO tcgen05)
// ============================================================================
__device__ __forceinline__ uint32_t smem_u32(const void* p) {
    uint32_t a;
    asm("{ .reg .u64 t; cvta.to.shared.u64 t, %1; cvt.u32.u64 %0, t; }" : "=r"(a) : "l"(p));
    return a;
}
__device__ __forceinline__ void cp16(uint32_t dst, const void* src) {
    asm volatile("cp.async.cg.shared.global [%0], [%1], 16;" :: "r"(dst), "l"(src));
}
#define CP_COMMIT() asm volatile("cp.async.commit_group;" ::: "memory")
#define CP_WAIT1()  asm volatile("cp.async.wait_group 1;" ::: "memory")

#define LDSM_X4(r, addr) \
    asm volatile("ldmatrix.sync.aligned.m8n8.x4.shared.b16 {%0,%1,%2,%3}, [%4];" \
        : "=r"((r)[0]), "=r"((r)[1]), "=r"((r)[2]), "=r"((r)[3]) : "r"(addr))

#define MMA16816(c, a, b0, b1) \
    asm volatile("mma.sync.aligned.m16n8k16.row.col.f32.bf16.bf16.f32 " \
        "{%0,%1,%2,%3}, {%4,%5,%6,%7}, {%8,%9}, {%0,%1,%2,%3};" \
        : "+f"((c)[0]), "+f"((c)[1]), "+f"((c)[2]), "+f"((c)[3]) \
        : "r"((a)[0]), "r"((a)[1]), "r"((a)[2]), "r"((a)[3]), "r"(b0), "r"(b1))

// ============================================================================
// Packed tile layout (unchanged): operand [R rows, Ktot cols] K-major bf16 ->
// tiles [R/128][Ktot/64], each 16 KB = 128 rows * 128 B, SW128 swizzled.
// ============================================================================
#define TILE_BYTES 16384
#define NSTAGE 3
#define SMEM_BYTES (1024 + 2 * NSTAGE * TILE_BYTES)   // align slack + 6 tiles

// Split fp32 [R, KT*64] into hi/lo packed tiles. causal: skip unread tiles.
__global__ void split_kernel(const float* __restrict__ in,
                             __nv_bfloat16* __restrict__ hi, __nv_bfloat16* __restrict__ lo,
                             int KT, int causal)
{
    const int kt = blockIdx.x, rt = blockIdx.y;
    if (causal && kt * 64 >= (rt + 1) * 128) return;
    const int ld = KT * 64;
    const float* src = in + (size_t)(rt * 128) * ld + kt * 64;
    char* hb = (char*)hi + (size_t)(rt * KT + kt) * TILE_BYTES;
    char* lb = (char*)lo + (size_t)(rt * KT + kt) * TILE_BYTES;
    for (int e = threadIdx.x; e < 8192; e += 256) {
        const int row = e >> 6, col = e & 63;
        const float v = src[row * ld + col];
        const __nv_bfloat16 h = __float2bfloat16(v);
        const __nv_bfloat16 l = __float2bfloat16(v - __bfloat162float(h));
        const int idx = row * 128 + col * 2;
        const int sw = idx ^ ((idx >> 3) & 0x70);
        *(__nv_bfloat16*)(hb + sw) = h;
        *(__nv_bfloat16*)(lb + sw) = l;
    }
}

// Transpose-split: fp32 [Kdim rows, N cols] -> operand [N rows, Kdim] tiles.
__global__ void tsplit_kernel(const float* __restrict__ in, int N,
                              __nv_bfloat16* __restrict__ hi, __nv_bfloat16* __restrict__ lo,
                              int KT)
{
    const int kt = blockIdx.x, nt = blockIdx.y;
    __shared__ float ts[64][133];
    const float* src = in + (size_t)(kt * 64) * N + nt * 128;
    for (int e = threadIdx.x; e < 8192; e += 256) {
        const int kk = e >> 7, nn = e & 127;
        ts[kk][nn] = src[kk * N + nn];
    }
    __syncthreads();
    char* hb = (char*)hi + (size_t)(nt * KT + kt) * TILE_BYTES;
    char* lb = (char*)lo + (size_t)(nt * KT + kt) * TILE_BYTES;
    for (int e = threadIdx.x; e < 8192; e += 256) {
        const int row = e >> 6, col = e & 63;
        const float v = ts[col][row];
        const __nv_bfloat16 h = __float2bfloat16(v);
        const __nv_bfloat16 l = __float2bfloat16(v - __bfloat162float(h));
        const int idx = row * 128 + col * 2;
        const int sw = idx ^ ((idx >> 3) & 0x70);
        *(__nv_bfloat16*)(hb + sw) = h;
        *(__nv_bfloat16*)(lb + sw) = l;
    }
}

// ============================================================================
// HMMA GEMM: D[128,128] fp32 = sum over 3 hi/lo combos of A * B^T (bf16).
// 256 threads = 8 warps (4m x 2n), warp tile 32x64, BK=64, 3-stage cp.async.
// MODE 0: +bias -> q/k/v   MODE 1: scale+mask -> att (lower tiles)
// MODE 2: -> out, causal K bound, by reversed.
// ============================================================================
template<int MODE>
__global__ __launch_bounds__(256, 1)
void mm_kernel(const char* __restrict__ Ah, const char* __restrict__ Al,
               const char* __restrict__ Bh, const char* __restrict__ Bl,
               int KT,
               float* out0, float* out1, float* out2,
               const float* __restrict__ bias, const int* __restrict__ n_padd_ptr)
{
    extern __shared__ char smem_raw[];
    const int tid = threadIdx.x;
    const int wid = tid >> 5, lane = tid & 31;
    const int wm = wid & 3, wn = wid >> 2;

    const int bx = blockIdx.x;
    int by = blockIdx.y;
    if (MODE == 1 && bx > by) return;
    if (MODE == 2) by = gridDim.y - 1 - by;
    const int ktiles = (MODE == 2) ? 2 * (by + 1) : KT;
    const int total = 3 * ktiles;

    uint32_t sb = smem_u32(smem_raw);
    sb = (sb + 1023u) & ~1023u;
    const uint32_t SA = sb;
    const uint32_t SBB = sb + NSTAGE * TILE_BYTES;

    const char* Asel[3] = {Ah, Ah, Al};
    const char* Bsel[3] = {Bh, Bl, Bh};

    // Precompute swizzled per-lane ldmatrix offsets (within a 16 KB tile).
    // A fragment (m16k16): lanes 0-15 rows m0..15 @k0, lanes 16-31 same rows @k0+8
    uint32_t a_off[2][4], b_off[4][4];
    #pragma unroll
    for (int mi = 0; mi < 2; mi++)
        #pragma unroll
        for (int ks = 0; ks < 4; ks++) {
            const int row = wm * 32 + mi * 16 + (lane & 15);
            const int col = ks * 16 + ((lane >> 4) << 3);
            const int idx = row * 128 + col * 2;
            a_off[mi][ks] = idx ^ ((idx >> 3) & 0x70);
        }
    // B fragments (two n8 octets per x4): rows = n, cols = k
    #pragma unroll
    for (int nj = 0; nj < 4; nj++)
        #pragma unroll
        for (int ks = 0; ks < 4; ks++) {
            const int row = wn * 64 + nj * 16 + (lane & 7) + ((lane >> 4) << 3);
            const int col = ks * 16 + (((lane >> 3) & 1) << 3);
            const int idx = row * 128 + col * 2;
            b_off[nj][ks] = idx ^ ((idx >> 3) & 0x70);
        }

    float acc[2][8][4];
    #pragma unroll
    for (int mi = 0; mi < 2; mi++)
        #pragma unroll
        for (int ni = 0; ni < 8; ni++)
            #pragma unroll
            for (int e = 0; e < 4; e++) acc[mi][ni][e] = 0.f;

    auto issue = [&](int i) {
        const int c = i / ktiles, kt = i - c * ktiles;
        const char* Ab = Asel[c] + ((size_t)by * KT + kt) * TILE_BYTES;
        const char* Bb = Bsel[c] + ((size_t)bx * KT + kt) * TILE_BYTES;
        const int s = i % NSTAGE;
        const uint32_t sa = SA + s * TILE_BYTES, sbuf = SBB + s * TILE_BYTES;
        #pragma unroll
        for (int w = 0; w < 4; w++) {
            cp16(sa   + w * 4096 + tid * 16, Ab + w * 4096 + tid * 16);
            cp16(sbuf + w * 4096 + tid * 16, Bb + w * 4096 + tid * 16);
        }
        CP_COMMIT();
    };

    issue(0);
    issue(1);

    for (int i = 0; i < total; i++) {
        CP_WAIT1();                 // newest group may be pending; group i done
        __syncthreads();
        const int s = i % NSTAGE;
        const uint32_t sa = SA + s * TILE_BYTES, sbuf = SBB + s * TILE_BYTES;

        #pragma unroll
        for (int ks = 0; ks < 4; ks++) {
            uint32_t afr[2][4], bfr[4][4];
            #pragma unroll
            for (int mi = 0; mi < 2; mi++) LDSM_X4(afr[mi], sa + a_off[mi][ks]);
            #pragma unroll
            for (int nj = 0; nj < 4; nj++) LDSM_X4(bfr[nj], sbuf + b_off[nj][ks]);
            #pragma unroll
            for (int mi = 0; mi < 2; mi++)
                #pragma unroll
                for (int ni = 0; ni < 8; ni++)
                    MMA16816(acc[mi][ni], afr[mi],
                             bfr[ni >> 1][(ni & 1) * 2],
                             bfr[ni >> 1][(ni & 1) * 2 + 1]);
        }

        if (i + 2 < total) issue(i + 2);
        else CP_COMMIT();           // empty group keeps wait_group accounting valid
    }

    // ---- epilogue ----
    const int qr = lane >> 2;          // 0..7
    const int qc = (lane & 3) * 2;     // 0,2,4,6

    #pragma unroll
    for (int mi = 0; mi < 2; mi++) {
        #pragma unroll
        for (int hf = 0; hf < 2; hf++) {
            const int r = by * 128 + wm * 32 + mi * 16 + qr + hf * 8;
            #pragma unroll
            for (int ni = 0; ni < 8; ni++) {
                const int cg = bx * 128 + wn * 64 + ni * 8 + qc;
                float v0 = acc[mi][ni][hf * 2];
                float v1 = acc[mi][ni][hf * 2 + 1];
                if (MODE == 0) {
                    const int h = bx >> 3;
                    float* dst = (h == 0) ? out0 : (h == 1) ? out1 : out2;
                    const int lc = cg - h * C_DIM;
                    float2 o = { v0 + bias[cg], v1 + bias[cg + 1] };
                    *(float2*)(dst + (size_t)r * C_DIM + lc) = o;
                } else if (MODE == 1) {
                    const int np = *n_padd_ptr;
                    const float scale = 0.03125f;       // 1/sqrt(1024)
                    float2 o = { v0 * scale, v1 * scale };
                    if (r < np || cg     < np) o.x = NEG_INF_F;
                    if (r < np || cg + 1 < np) o.y = NEG_INF_F;
                    *(float2*)(out0 + (size_t)r * T_DIM + cg) = o;
                } else {
                    float2 o = { v0, v1 };
                    *(float2*)(out0 + (size_t)r * C_DIM + cg) = o;
                }
            }
        }
    }
}

// ============================================================================
// Row softmax over [0, row]; zero-fill to next 128 boundary for PV.
// ============================================================================
__global__ __launch_bounds__(256) void softmax_kernel(float* __restrict__ att)
{
    const int r = blockIdx.x;
    float* __restrict__ row = att + (size_t)r * T_DIM;
    const int n = r + 1;
    const int fill_end = ((r >> 7) + 1) << 7;
    const int tid = threadIdx.x;
    __shared__ float red[256];

    float m = -INFINITY;
    for (int j = tid; j < n; j += 256) m = fmaxf(m, row[j]);
    red[tid] = m; __syncthreads();
    #pragma unroll
    for (int s = 128; s > 0; s >>= 1) {
        if (tid < s) red[tid] = fmaxf(red[tid], red[tid + s]);
        __syncthreads();
    }
    m = red[0];
    __syncthreads();

    float sum = 0.f;
    for (int j = tid; j < n; j += 256) {
        const float e = __expf(row[j] - m);
        row[j] = e;
        sum += e;
    }
    red[tid] = sum; __syncthreads();
    #pragma unroll
    for (int s = 128; s > 0; s >>= 1) {
        if (tid < s) red[tid] += red[tid + s];
        __syncthreads();
    }
    const float inv = 1.0f / red[0];

    for (int j = tid; j < n; j += 256) row[j] *= inv;
    for (int j = n + tid; j < fill_end; j += 256) row[j] = 0.f;
}

// ============================================================================
extern "C" void kernel_launch(void* const* d_in, const int* in_sizes, int n_in,
                              void* d_out, int out_size)
{
    const float* x    = (const float*)d_in[0];   // [T, C]
    const float* W    = (const float*)d_in[1];   // [C, 3C]
    const float* bias = (const float*)d_in[2];   // [3C]
    const int* n_padd = (const int*)d_in[3];
    float* out = (float*)d_out;                  // [T, C]

    void* base = nullptr;
    cudaGetSymbolAddress(&base, g_buf);
    char* b = (char*)base;

    float* qf   = (float*)(b + OFF_Q);
    float* kf   = (float*)(b + OFF_K);
    float* vf   = (float*)(b + OFF_V);
    float* att  = (float*)(b + OFF_ATT);
    __nv_bfloat16* xh  = (__nv_bfloat16*)(b + OFF_XH);
    __nv_bfloat16* xl  = (__nv_bfloat16*)(b + OFF_XL);
    __nv_bfloat16* wth = (__nv_bfloat16*)(b + OFF_WTH);
    __nv_bfloat16* wtl = (__nv_bfloat16*)(b + OFF_WTL);
    __nv_bfloat16* qh  = (__nv_bfloat16*)(b + OFF_QH);
    __nv_bfloat16* ql  = (__nv_bfloat16*)(b + OFF_QL);
    __nv_bfloat16* kh  = (__nv_bfloat16*)(b + OFF_KH);
    __nv_bfloat16* kl  = (__nv_bfloat16*)(b + OFF_KL);
    __nv_bfloat16* vth = (__nv_bfloat16*)(b + OFF_VTH);
    __nv_bfloat16* vtl = (__nv_bfloat16*)(b + OFF_VTL);
    __nv_bfloat16* ath = (__nv_bfloat16*)(b + OFF_ATH);
    __nv_bfloat16* atl = (__nv_bfloat16*)(b + OFF_ATL);

    cudaFuncSetAttribute(mm_kernel<0>, cudaFuncAttributeMaxDynamicSharedMemorySize, SMEM_BYTES);
    cudaFuncSetAttribute(mm_kernel<1>, cudaFuncAttributeMaxDynamicSharedMemorySize, SMEM_BYTES);
    cudaFuncSetAttribute(mm_kernel<2>, cudaFuncAttributeMaxDynamicSharedMemorySize, SMEM_BYTES);

    // 1) operand prep for QKV
    tsplit_kernel<<<dim3(16, 24), 256>>>(W, 3 * C_DIM, wth, wtl, 16);   // W^T [3072,1024]
    split_kernel <<<dim3(16, 32), 256>>>(x, xh, xl, 16, 0);             // x   [4096,1024]

    // 2) QKV GEMM -> q, k, v fp32
    mm_kernel<0><<<dim3(24, 32), 256, SMEM_BYTES>>>(
        (const char*)xh, (const char*)xl, (const char*)wth, (const char*)wtl,
        16, qf, kf, vf, bias, nullptr);

    // 3) operand prep for QK and PV(B side)
    split_kernel <<<dim3(16, 32), 256>>>(qf, qh, ql, 16, 0);
    split_kernel <<<dim3(16, 32), 256>>>(kf, kh, kl, 16, 0);
    tsplit_kernel<<<dim3(64, 8), 256>>>(vf, C_DIM, vth, vtl, 64);       // v^T [1024,4096]

    // 4) QK GEMM (lower tiles) -> att fp32 (scaled, padding-masked)
    mm_kernel<1><<<dim3(32, 32), 256, SMEM_BYTES>>>(
        (const char*)qh, (const char*)ql, (const char*)kh, (const char*)kl,
        16, att, nullptr, nullptr, nullptr, n_padd);

    // 5) softmax (causal) + zero-fill to tile edge
    softmax_kernel<<<T_DIM, 256>>>(att);

    // 6) att split (only tiles PV reads)
    split_kernel<<<dim3(64, 32), 256>>>(att, ath, atl, 64, 1);

    // 7) PV GEMM -> y
    mm_kernel<2><<<dim3(8, 32), 256, SMEM_BYTES>>>(
        (const char*)ath, (const char*)atl, (const char*)vth, (const char*)vtl,
        64, out, nullptr, nullptr, nullptr, nullptr);
}

// round 9
// speedup vs baseline: 2.1834x; 1.0024x over previous
#include <cuda_runtime.h>
#include <cuda_bf16.h>
#include <cstdint>
#include <math.h>

#define T_DIM 4096
#define C_DIM 1024
#define NEG_INF_F (-1e30f)

// ============================================================================
// Scratch buffer (single device symbol). ~252 MB.
// ============================================================================
#define MB_ (1048576ull)
#define OFF_Q    (0ull)            // fp32 q        16 MB
#define OFF_K    (16*MB_)          // fp32 k        16 MB
#define OFF_V    (32*MB_)          // fp32 v        16 MB
#define OFF_ATT  (48*MB_)          // fp32 att      64 MB
#define OFF_XH   (112*MB_)
#define OFF_XL   (120*MB_)
#define OFF_WTH  (128*MB_)
#define OFF_WTL  (134*MB_)
#define OFF_QH   (140*MB_)
#define OFF_QL   (148*MB_)
#define OFF_KH   (156*MB_)
#define OFF_KL   (164*MB_)
#define OFF_VTH  (172*MB_)
#define OFF_VTL  (180*MB_)
#define OFF_ATH  (188*MB_)
#define OFF_ATL  (220*MB_)
#define BUF_TOTAL (252*MB_)

__device__ __align__(1024) char g_buf[BUF_TOTAL];

// ============================================================================
// Baseline-PTX helpers (sm_80-class: cp.async, ldmatrix, mma.sync — NO tcgen05)
// ============================================================================
__device__ __forceinline__ uint32_t smem_u32(const void* p) {
    uint32_t a;
    asm("{ .reg .u64 t; cvta.to.shared.u64 t, %1; cvt.u32.u64 %0, t; }" : "=r"(a) : "l"(p));
    return a;
}
__device__ __forceinline__ void cp16(uint32_t dst, const void* src) {
    asm volatile("cp.async.cg.shared.global [%0], [%1], 16;" :: "r"(dst), "l"(src));
}
#define CP_COMMIT() asm volatile("cp.async.commit_group;" ::: "memory")
#define CP_WAIT1()  asm volatile("cp.async.wait_group 1;" ::: "memory")

#define LDSM_X4(r, addr) \
    asm volatile("ldmatrix.sync.aligned.m8n8.x4.shared.b16 {%0,%1,%2,%3}, [%4];" \
        : "=r"((r)[0]), "=r"((r)[1]), "=r"((r)[2]), "=r"((r)[3]) : "r"(addr))

#define MMA16816(c, a, b0, b1) \
    asm volatile("mma.sync.aligned.m16n8k16.row.col.f32.bf16.bf16.f32 " \
        "{%0,%1,%2,%3}, {%4,%5,%6,%7}, {%8,%9}, {%0,%1,%2,%3};" \
        : "+f"((c)[0]), "+f"((c)[1]), "+f"((c)[2]), "+f"((c)[3]) \
        : "r"((a)[0]), "r"((a)[1]), "r"((a)[2]), "r"((a)[3]), "r"(b0), "r"(b1))

// ============================================================================
// Packed tile layout (unchanged): operand [R rows, Ktot cols] K-major bf16 ->
// tiles [R/128][Ktot/64], each 16 KB = 128 rows * 128 B, SW128 swizzled.
// ============================================================================
#define TILE_BYTES 16384
#define NSTAGE 3
#define SMEM_BYTES (1024 + 2 * NSTAGE * TILE_BYTES)   // align slack + 6 tiles

// Split fp32 [R, KT*64] into hi/lo packed tiles. causal: skip unread tiles.
__global__ void split_kernel(const float* __restrict__ in,
                             __nv_bfloat16* __restrict__ hi, __nv_bfloat16* __restrict__ lo,
                             int KT, int causal)
{
    const int kt = blockIdx.x, rt = blockIdx.y;
    if (causal && kt * 64 >= (rt + 1) * 128) return;
    const int ld = KT * 64;
    const float* src = in + (size_t)(rt * 128) * ld + kt * 64;
    char* hb = (char*)hi + (size_t)(rt * KT + kt) * TILE_BYTES;
    char* lb = (char*)lo + (size_t)(rt * KT + kt) * TILE_BYTES;
    for (int e = threadIdx.x; e < 8192; e += 256) {
        const int row = e >> 6, col = e & 63;
        const float v = src[row * ld + col];
        const __nv_bfloat16 h = __float2bfloat16(v);
        const __nv_bfloat16 l = __float2bfloat16(v - __bfloat162float(h));
        const int idx = row * 128 + col * 2;
        const int sw = idx ^ ((idx >> 3) & 0x70);
        *(__nv_bfloat16*)(hb + sw) = h;
        *(__nv_bfloat16*)(lb + sw) = l;
    }
}

// Transpose-split: fp32 [Kdim rows, N cols] -> operand [N rows, Kdim] tiles.
__global__ void tsplit_kernel(const float* __restrict__ in, int N,
                              __nv_bfloat16* __restrict__ hi, __nv_bfloat16* __restrict__ lo,
                              int KT)
{
    const int kt = blockIdx.x, nt = blockIdx.y;
    __shared__ float ts[64][133];
    const float* src = in + (size_t)(kt * 64) * N + nt * 128;
    for (int e = threadIdx.x; e < 8192; e += 256) {
        const int kk = e >> 7, nn = e & 127;
        ts[kk][nn] = src[kk * N + nn];
    }
    __syncthreads();
    char* hb = (char*)hi + (size_t)(nt * KT + kt) * TILE_BYTES;
    char* lb = (char*)lo + (size_t)(nt * KT + kt) * TILE_BYTES;
    for (int e = threadIdx.x; e < 8192; e += 256) {
        const int row = e >> 6, col = e & 63;
        const float v = ts[col][row];
        const __nv_bfloat16 h = __float2bfloat16(v);
        const __nv_bfloat16 l = __float2bfloat16(v - __bfloat162float(h));
        const int idx = row * 128 + col * 2;
        const int sw = idx ^ ((idx >> 3) & 0x70);
        *(__nv_bfloat16*)(hb + sw) = h;
        *(__nv_bfloat16*)(lb + sw) = l;
    }
}

// ============================================================================
// HMMA GEMM: D[128,128] fp32 = sum over 3 hi/lo combos of A * B^T (bf16).
// 256 threads = 8 warps (4m x 2n), warp tile 32x64, BK=64, 3-stage cp.async.
// MODE 0: +bias -> q/k/v   MODE 1: scale+mask -> att (lower tiles)
// MODE 2: -> out, causal K bound, by reversed.
// ============================================================================
template<int MODE>
__global__ __launch_bounds__(256, 1)
void mm_kernel(const char* __restrict__ Ah, const char* __restrict__ Al,
               const char* __restrict__ Bh, const char* __restrict__ Bl,
               int KT,
               float* out0, float* out1, float* out2,
               const float* __restrict__ bias, const int* __restrict__ n_padd_ptr)
{
    extern __shared__ char smem_raw[];
    const int tid = threadIdx.x;
    const int wid = tid >> 5, lane = tid & 31;
    const int wm = wid & 3, wn = wid >> 2;

    const int bx = blockIdx.x;
    int by = blockIdx.y;
    if (MODE == 1 && bx > by) return;
    if (MODE == 2) by = gridDim.y - 1 - by;
    const int ktiles = (MODE == 2) ? 2 * (by + 1) : KT;
    const int total = 3 * ktiles;

    uint32_t sb = smem_u32(smem_raw);
    sb = (sb + 1023u) & ~1023u;
    const uint32_t SA = sb;
    const uint32_t SBB = sb + NSTAGE * TILE_BYTES;

    const char* Asel[3] = {Ah, Ah, Al};
    const char* Bsel[3] = {Bh, Bl, Bh};

    // Precompute swizzled per-lane ldmatrix offsets (within a 16 KB tile).
    // A fragment (m16k16): lanes 0-15 rows m0..15 @k0, lanes 16-31 same rows @k0+8
    uint32_t a_off[2][4], b_off[4][4];
    #pragma unroll
    for (int mi = 0; mi < 2; mi++)
        #pragma unroll
        for (int ks = 0; ks < 4; ks++) {
            const int row = wm * 32 + mi * 16 + (lane & 15);
            const int col = ks * 16 + ((lane >> 4) << 3);
            const int idx = row * 128 + col * 2;
            a_off[mi][ks] = idx ^ ((idx >> 3) & 0x70);
        }
    // B fragments (two n8 octets per x4): rows = n, cols = k
    #pragma unroll
    for (int nj = 0; nj < 4; nj++)
        #pragma unroll
        for (int ks = 0; ks < 4; ks++) {
            const int row = wn * 64 + nj * 16 + (lane & 7) + ((lane >> 4) << 3);
            const int col = ks * 16 + (((lane >> 3) & 1) << 3);
            const int idx = row * 128 + col * 2;
            b_off[nj][ks] = idx ^ ((idx >> 3) & 0x70);
        }

    float acc[2][8][4];
    #pragma unroll
    for (int mi = 0; mi < 2; mi++)
        #pragma unroll
        for (int ni = 0; ni < 8; ni++)
            #pragma unroll
            for (int e = 0; e < 4; e++) acc[mi][ni][e] = 0.f;

    auto issue = [&](int i) {
        const int c = i / ktiles, kt = i - c * ktiles;
        const char* Ab = Asel[c] + ((size_t)by * KT + kt) * TILE_BYTES;
        const char* Bb = Bsel[c] + ((size_t)bx * KT + kt) * TILE_BYTES;
        const int s = i % NSTAGE;
        const uint32_t sa = SA + s * TILE_BYTES, sbuf = SBB + s * TILE_BYTES;
        #pragma unroll
        for (int w = 0; w < 4; w++) {
            cp16(sa   + w * 4096 + tid * 16, Ab + w * 4096 + tid * 16);
            cp16(sbuf + w * 4096 + tid * 16, Bb + w * 4096 + tid * 16);
        }
        CP_COMMIT();
    };

    issue(0);
    issue(1);

    for (int i = 0; i < total; i++) {
        CP_WAIT1();                 // newest group may be pending; group i done
        __syncthreads();
        const int s = i % NSTAGE;
        const uint32_t sa = SA + s * TILE_BYTES, sbuf = SBB + s * TILE_BYTES;

        #pragma unroll
        for (int ks = 0; ks < 4; ks++) {
            uint32_t afr[2][4], bfr[4][4];
            #pragma unroll
            for (int mi = 0; mi < 2; mi++) LDSM_X4(afr[mi], sa + a_off[mi][ks]);
            #pragma unroll
            for (int nj = 0; nj < 4; nj++) LDSM_X4(bfr[nj], sbuf + b_off[nj][ks]);
            #pragma unroll
            for (int mi = 0; mi < 2; mi++)
                #pragma unroll
                for (int ni = 0; ni < 8; ni++)
                    MMA16816(acc[mi][ni], afr[mi],
                             bfr[ni >> 1][(ni & 1) * 2],
                             bfr[ni >> 1][(ni & 1) * 2 + 1]);
        }

        if (i + 2 < total) issue(i + 2);
        else CP_COMMIT();           // empty group keeps wait_group accounting valid
    }

    // ---- epilogue ----
    const int qr = lane >> 2;          // 0..7
    const int qc = (lane & 3) * 2;     // 0,2,4,6

    #pragma unroll
    for (int mi = 0; mi < 2; mi++) {
        #pragma unroll
        for (int hf = 0; hf < 2; hf++) {
            const int r = by * 128 + wm * 32 + mi * 16 + qr + hf * 8;
            #pragma unroll
            for (int ni = 0; ni < 8; ni++) {
                const int cg = bx * 128 + wn * 64 + ni * 8 + qc;
                float v0 = acc[mi][ni][hf * 2];
                float v1 = acc[mi][ni][hf * 2 + 1];
                if (MODE == 0) {
                    const int h = bx >> 3;
                    float* dst = (h == 0) ? out0 : (h == 1) ? out1 : out2;
                    const int lc = cg - h * C_DIM;
                    float2 o = { v0 + bias[cg], v1 + bias[cg + 1] };
                    *(float2*)(dst + (size_t)r * C_DIM + lc) = o;
                } else if (MODE == 1) {
                    const int np = *n_padd_ptr;
                    const float scale = 0.03125f;       // 1/sqrt(1024)
                    float2 o = { v0 * scale, v1 * scale };
                    if (r < np || cg     < np) o.x = NEG_INF_F;
                    if (r < np || cg + 1 < np) o.y = NEG_INF_F;
                    *(float2*)(out0 + (size_t)r * T_DIM + cg) = o;
                } else {
                    float2 o = { v0, v1 };
                    *(float2*)(out0 + (size_t)r * C_DIM + cg) = o;
                }
            }
        }
    }
}

// ============================================================================
// Row softmax over [0, row]; zero-fill to next 128 boundary for PV.
// ============================================================================
__global__ __launch_bounds__(256) void softmax_kernel(float* __restrict__ att)
{
    const int r = blockIdx.x;
    float* __restrict__ row = att + (size_t)r * T_DIM;
    const int n = r + 1;
    const int fill_end = ((r >> 7) + 1) << 7;
    const int tid = threadIdx.x;
    __shared__ float red[256];

    float m = -INFINITY;
    for (int j = tid; j < n; j += 256) m = fmaxf(m, row[j]);
    red[tid] = m; __syncthreads();
    #pragma unroll
    for (int s = 128; s > 0; s >>= 1) {
        if (tid < s) red[tid] = fmaxf(red[tid], red[tid + s]);
        __syncthreads();
    }
    m = red[0];
    __syncthreads();

    float sum = 0.f;
    for (int j = tid; j < n; j += 256) {
        const float e = __expf(row[j] - m);
        row[j] = e;
        sum += e;
    }
    red[tid] = sum; __syncthreads();
    #pragma unroll
    for (int s = 128; s > 0; s >>= 1) {
        if (tid < s) red[tid] += red[tid + s];
        __syncthreads();
    }
    const float inv = 1.0f / red[0];

    for (int j = tid; j < n; j += 256) row[j] *= inv;
    for (int j = n + tid; j < fill_end; j += 256) row[j] = 0.f;
}

// ============================================================================
extern "C" void kernel_launch(void* const* d_in, const int* in_sizes, int n_in,
                              void* d_out, int out_size)
{
    const float* x    = (const float*)d_in[0];   // [T, C]
    const float* W    = (const float*)d_in[1];   // [C, 3C]
    const float* bias = (const float*)d_in[2];   // [3C]
    const int* n_padd = (const int*)d_in[3];
    float* out = (float*)d_out;                  // [T, C]

    void* base = nullptr;
    cudaGetSymbolAddress(&base, g_buf);
    char* b = (char*)base;

    float* qf   = (float*)(b + OFF_Q);
    float* kf   = (float*)(b + OFF_K);
    float* vf   = (float*)(b + OFF_V);
    float* att  = (float*)(b + OFF_ATT);
    __nv_bfloat16* xh  = (__nv_bfloat16*)(b + OFF_XH);
    __nv_bfloat16* xl  = (__nv_bfloat16*)(b + OFF_XL);
    __nv_bfloat16* wth = (__nv_bfloat16*)(b + OFF_WTH);
    __nv_bfloat16* wtl = (__nv_bfloat16*)(b + OFF_WTL);
    __nv_bfloat16* qh  = (__nv_bfloat16*)(b + OFF_QH);
    __nv_bfloat16* ql  = (__nv_bfloat16*)(b + OFF_QL);
    __nv_bfloat16* kh  = (__nv_bfloat16*)(b + OFF_KH);
    __nv_bfloat16* kl  = (__nv_bfloat16*)(b + OFF_KL);
    __nv_bfloat16* vth = (__nv_bfloat16*)(b + OFF_VTH);
    __nv_bfloat16* vtl = (__nv_bfloat16*)(b + OFF_VTL);
    __nv_bfloat16* ath = (__nv_bfloat16*)(b + OFF_ATH);
    __nv_bfloat16* atl = (__nv_bfloat16*)(b + OFF_ATL);

    cudaFuncSetAttribute(mm_kernel<0>, cudaFuncAttributeMaxDynamicSharedMemorySize, SMEM_BYTES);
    cudaFuncSetAttribute(mm_kernel<1>, cudaFuncAttributeMaxDynamicSharedMemorySize, SMEM_BYTES);
    cudaFuncSetAttribute(mm_kernel<2>, cudaFuncAttributeMaxDynamicSharedMemorySize, SMEM_BYTES);

    // 1) operand prep for QKV
    tsplit_kernel<<<dim3(16, 24), 256>>>(W, 3 * C_DIM, wth, wtl, 16);   // W^T [3072,1024]
    split_kernel <<<dim3(16, 32), 256>>>(x, xh, xl, 16, 0);             // x   [4096,1024]

    // 2) QKV GEMM -> q, k, v fp32
    mm_kernel<0><<<dim3(24, 32), 256, SMEM_BYTES>>>(
        (const char*)xh, (const char*)xl, (const char*)wth, (const char*)wtl,
        16, qf, kf, vf, bias, nullptr);

    // 3) operand prep for QK and PV(B side)
    split_kernel <<<dim3(16, 32), 256>>>(qf, qh, ql, 16, 0);
    split_kernel <<<dim3(16, 32), 256>>>(kf, kh, kl, 16, 0);
    tsplit_kernel<<<dim3(64, 8), 256>>>(vf, C_DIM, vth, vtl, 64);       // v^T [1024,4096]

    // 4) QK GEMM (lower tiles) -> att fp32 (scaled, padding-masked)
    mm_kernel<1><<<dim3(32, 32), 256, SMEM_BYTES>>>(
        (const char*)qh, (const char*)ql, (const char*)kh, (const char*)kl,
        16, att, nullptr, nullptr, nullptr, n_padd);

    // 5) softmax (causal) + zero-fill to tile edge
    softmax_kernel<<<T_DIM, 256>>>(att);

    // 6) att split (only tiles PV reads)
    split_kernel<<<dim3(64, 32), 256>>>(att, ath, atl, 64, 1);

    // 7) PV GEMM -> y
    mm_kernel<2><<<dim3(8, 32), 256, SMEM_BYTES>>>(
        (const char*)ath, (const char*)atl, (const char*)vth, (const char*)vtl,
        64, out, nullptr, nullptr, nullptr, nullptr);
}